// round 16
// baseline (speedup 1.0000x reference)
#include <cuda_runtime.h>
#include <cuda_bf16.h>
#include <cstdint>

#define S_LEN 2048
#define B_SZ  64
#define I_DIM 128
#define H_DIM 256
#define O_DIM 64
#define NROWS (S_LEN * B_SZ)   // 131072 rows, n = b*S + s

// Scratch (static device arrays: allocation-free rule).
__device__ float g_bufA[(size_t)NROWS * H_DIM];
__device__ float g_bufB[(size_t)NROWS * H_DIM];
__device__ float g_bufC[(size_t)NROWS * H_DIM];
__device__ float g_bufD[(size_t)NROWS * H_DIM];
// Head-fusion scratch
__device__ float g_M[H_DIM * H_DIM];     // fc2W @ fc1W
__device__ float g_hW[O_DIM * H_DIM];    // fc3W @ g_M
__device__ float g_hb[O_DIM];            // fused bias

// ---- packed fp32x2 helpers (sm_100+) --------------------------------------
__device__ __forceinline__ void fma2(unsigned long long& d,
                                     unsigned long long a,
                                     unsigned long long b)
{
    asm("fma.rn.f32x2 %0, %1, %2, %0;" : "+l"(d) : "l"(a), "l"(b));
}
__device__ __forceinline__ unsigned long long splat2(float x)
{
    unsigned long long r;
    asm("mov.b64 %0, {%1, %1};" : "=l"(r) : "f"(x));
    return r;
}
__device__ __forceinline__ float2 unpack2(unsigned long long v)
{
    float2 r;
    asm("mov.b64 {%0, %1}, %2;" : "=f"(r.x), "=f"(r.y) : "l"(v));
    return r;
}
// Branchless fast tanh: 1 - 2/(exp(2x)+1). Saturates correctly at +-1.
__device__ __forceinline__ float fast_tanh(float x)
{
    float e = __expf(2.f * x);
    return 1.f - __fdividef(2.f, e + 1.f);
}
// mbarrier parity wait (acquire.cluster: orders peer st.async data)
__device__ __forceinline__ void mbar_wait(uint32_t addr, uint32_t parity)
{
    uint32_t done;
    asm volatile(
        "{\n\t.reg .pred p;\n\t"
        "mbarrier.try_wait.parity.acquire.cluster.shared::cta.b64 p, [%1], %2;\n\t"
        "selp.b32 %0, 1, 0, p;\n\t}"
        : "=r"(done) : "r"(addr), "r"(parity) : "memory");
    if (!done) {
        asm volatile(
            "{\n\t.reg .pred P1;\n\t"
            "WL_%=:\n\t"
            "mbarrier.try_wait.parity.acquire.cluster.shared::cta.b64 P1, [%0], %1, 0x989680;\n\t"
            "@P1 bra.uni WD_%=;\n\t"
            "bra.uni WL_%=;\n\t"
            "WD_%=:\n\t}"
            :: "r"(addr), "r"(parity) : "memory");
    }
}

// ---------------------------------------------------------------------------
// GEMM: C[M,N] = A[M,K] @ W[N,K]^T + b1[n] (+ b2[n])
// BM=128, BN=128, BK=16, TM=TN=8, 256 threads. fp32x2 packed accumulation.
// (At the fp32 issue roofline per R7-R15 profiles -- frozen.)
// ---------------------------------------------------------------------------
__global__ __launch_bounds__(256, 2) void sgemm_bias(
    const float* __restrict__ A, const float* __restrict__ W,
    const float* __restrict__ b1, const float* __restrict__ b2,
    float* __restrict__ C, int M, int N, int K)
{
    constexpr int BM = 128, BN = 128, BK = 16, TM = 8, TN = 8;
    __shared__ __align__(16) float As[BK][BM + 4];
    __shared__ __align__(16) float Ws[BK][BN + 4];

    const int tid = threadIdx.x;
    const int tx  = tid & 15;   // n sub-tile
    const int ty  = tid >> 4;   // m sub-tile
    const int m0  = blockIdx.y * BM;
    const int n0  = blockIdx.x * BN;

    unsigned long long acc2[TM / 2][TN];
#pragma unroll
    for (int p = 0; p < TM / 2; p++)
#pragma unroll
        for (int j = 0; j < TN; j++) acc2[p][j] = 0ULL;

    for (int k0 = 0; k0 < K; k0 += BK) {
#pragma unroll
        for (int l = 0; l < 2; l++) {
            int idx = tid + l * 256;
            int r = idx >> 2;
            int c = (idx & 3) << 2;
            float4 v = *reinterpret_cast<const float4*>(
                A + (size_t)(m0 + r) * K + k0 + c);
            As[c + 0][r] = v.x; As[c + 1][r] = v.y;
            As[c + 2][r] = v.z; As[c + 3][r] = v.w;
        }
#pragma unroll
        for (int l = 0; l < 2; l++) {
            int idx = tid + l * 256;
            int r = idx >> 2;
            int c = (idx & 3) << 2;
            float4 v = make_float4(0.f, 0.f, 0.f, 0.f);
            if (n0 + r < N)
                v = *reinterpret_cast<const float4*>(
                    W + (size_t)(n0 + r) * K + k0 + c);
            Ws[c + 0][r] = v.x; Ws[c + 1][r] = v.y;
            Ws[c + 2][r] = v.z; Ws[c + 3][r] = v.w;
        }
        __syncthreads();

#pragma unroll
        for (int k = 0; k < BK; k++) {
            ulonglong2 ra = *reinterpret_cast<const ulonglong2*>(&As[k][ty * TM]);
            ulonglong2 rb = *reinterpret_cast<const ulonglong2*>(&As[k][ty * TM + 4]);
            unsigned long long rm2[4] = { ra.x, ra.y, rb.x, rb.y };

            float4 n0v = *reinterpret_cast<const float4*>(&Ws[k][tx * TN]);
            float4 n1v = *reinterpret_cast<const float4*>(&Ws[k][tx * TN + 4]);
            unsigned long long rn2[TN];
            rn2[0] = splat2(n0v.x); rn2[1] = splat2(n0v.y);
            rn2[2] = splat2(n0v.z); rn2[3] = splat2(n0v.w);
            rn2[4] = splat2(n1v.x); rn2[5] = splat2(n1v.y);
            rn2[6] = splat2(n1v.z); rn2[7] = splat2(n1v.w);

#pragma unroll
            for (int p = 0; p < TM / 2; p++)
#pragma unroll
                for (int j = 0; j < TN; j++)
                    fma2(acc2[p][j], rm2[p], rn2[j]);
        }
        __syncthreads();
    }

    const int gn0 = n0 + tx * TN;
    if (gn0 < N) {
        float bias[TN];
#pragma unroll
        for (int j = 0; j < TN; j++) {
            int gn = gn0 + j;
            bias[j] = b1[gn] + (b2 ? b2[gn] : 0.f);
        }
#pragma unroll
        for (int p = 0; p < TM / 2; p++) {
            float r0[TN], r1[TN];
#pragma unroll
            for (int j = 0; j < TN; j++) {
                float2 u = unpack2(acc2[p][j]);
                r0[j] = u.x + bias[j];
                r1[j] = u.y + bias[j];
            }
            int gm = m0 + ty * TM + 2 * p;
            float4 o;
            o = make_float4(r0[0], r0[1], r0[2], r0[3]);
            *reinterpret_cast<float4*>(C + (size_t)gm * N + gn0) = o;
            o = make_float4(r0[4], r0[5], r0[6], r0[7]);
            *reinterpret_cast<float4*>(C + (size_t)gm * N + gn0 + 4) = o;
            o = make_float4(r1[0], r1[1], r1[2], r1[3]);
            *reinterpret_cast<float4*>(C + (size_t)(gm + 1) * N + gn0) = o;
            o = make_float4(r1[4], r1[5], r1[6], r1[7]);
            *reinterpret_cast<float4*>(C + (size_t)(gm + 1) * N + gn0 + 4) = o;
        }
    }
}

// ---------------------------------------------------------------------------
// Small NN matmul for head fusion: C[i,j] = sum_k A[i,k] * B[k,j]
// ---------------------------------------------------------------------------
__global__ __launch_bounds__(256) void matmul_nn(
    const float* __restrict__ A, const float* __restrict__ B,
    float* __restrict__ C)
{
    __shared__ float arow[H_DIM];
    const int i = blockIdx.x, j = threadIdx.x;
    arow[j] = A[i * H_DIM + j];
    __syncthreads();
    float s = 0.f;
#pragma unroll 8
    for (int k = 0; k < H_DIM; k++)
        s = fmaf(arow[k], B[(size_t)k * H_DIM + j], s);
    C[i * H_DIM + j] = s;
}

// Fused head bias: b' = F3 @ (F2 @ b1 + b2) + b3. One block, 256 threads.
__global__ __launch_bounds__(256) void head_bias(
    const float* __restrict__ F2, const float* __restrict__ b1,
    const float* __restrict__ b2, const float* __restrict__ F3,
    const float* __restrict__ b3, float* __restrict__ bout)
{
    __shared__ float bt[H_DIM];
    const int t = threadIdx.x;
    float s = b2[t];
    for (int k = 0; k < H_DIM; k++)
        s = fmaf(F2[(size_t)t * H_DIM + k], b1[k], s);
    bt[t] = s;
    __syncthreads();
    if (t < O_DIM) {
        float s2 = b3[t];
        for (int k = 0; k < H_DIM; k++)
            s2 = fmaf(F3[(size_t)t * H_DIM + k], bt[k], s2);
        bout[t] = s2;
    }
}

// ---------------------------------------------------------------------------
// Recurrent scan, R16: one warp per 16-k chunk, 4 rows per lane.
// H[t] = tanh(Z[t] + W @ H[t-1]); 2-CTA cluster per batch, 512 threads.
// Warp w = k-chunk c = w (k in [c*16, c*16+16)); lane l covers rows
// {l, l+32, l+64, l+96}. h loads are 4 warp-uniform LDS.128 per warp
// (halves CTA LDS traffic vs 2-warps-per-chunk: 64 vs 128 LDS.128/step).
// Split-wait preserved (sacred per R12/R14): chunk local iff (c>>3)==rank;
// only the 8 late warps wait peer st.async bytes on ping-pong mbarriers.
// stage[128][17]: gcd(17,32)=1 -> conflict-free STS/LDS per phase.
// Sync protocol bit-identical to R13 (best measured): hoisted arm, single
// mbar per phase, 512 B expect_tx, acquire.cluster waits, final drain.
// ---------------------------------------------------------------------------
__global__ void __cluster_dims__(2, 1, 1) __launch_bounds__(512, 1)
scan_rnn(const float* __restrict__ Z, const float* __restrict__ Wr,
         float* __restrict__ Hout)
{
    __shared__ __align__(16) float h_buf[2][H_DIM];
    __shared__ float stage[128][17];          // stride 17 -> conflict-free
    __shared__ __align__(8) unsigned long long mbar[2];

    const int tid = threadIdx.x;
    uint32_t rank_u;
    asm("mov.u32 %0, %%cluster_ctarank;" : "=r"(rank_u));
    const int rank  = (int)rank_u;
    const int batch = blockIdx.x >> 1;
    const int c    = tid >> 5;      // warp = k-chunk 0..15 (16 k each)
    const int l    = tid & 31;      // lane -> rows {l, l+32, l+64, l+96}
    // chunk local iff its k range lies in this CTA's produced half
    const bool is_late = ((c >> 3) != rank);

    // W: 4 rows x 16 k, packed fp32x2 pairs along k. 8 ull per row.
    unsigned long long wA[8], wB[8], wC[8], wD[8];
    {
        const int r0 = rank * 128 + l;
        const float* base = Wr + (size_t)r0 * H_DIM + c * 16;
#pragma unroll
        for (int j = 0; j < 4; j++) {
            ulonglong2 v;
            v = *reinterpret_cast<const ulonglong2*>(base + 0 * 32 * H_DIM + j * 4);
            wA[2 * j] = v.x; wA[2 * j + 1] = v.y;
            v = *reinterpret_cast<const ulonglong2*>(base + 1 * 32 * H_DIM + j * 4);
            wB[2 * j] = v.x; wB[2 * j + 1] = v.y;
            v = *reinterpret_cast<const ulonglong2*>(base + 2 * 32 * H_DIM + j * 4);
            wC[2 * j] = v.x; wC[2 * j + 1] = v.y;
            v = *reinterpret_cast<const ulonglong2*>(base + 3 * 32 * H_DIM + j * 4);
            wD[2 * j] = v.x; wD[2 * j + 1] = v.y;
        }
    }

    if (tid < H_DIM) { h_buf[0][tid] = 0.f; h_buf[1][tid] = 0.f; }
    if (tid == 0) {
        uint32_t mb;
        asm("{ .reg .u64 t; cvta.to.shared.u64 t, %1; cvt.u32.u64 %0, t; }"
            : "=r"(mb) : "l"(&mbar[0]));
        asm volatile("mbarrier.init.shared.b64 [%0], 1;" :: "r"(mb) : "memory");
        asm volatile("mbarrier.init.shared.b64 [%0], 1;" :: "r"(mb + 8) : "memory");
    }
    __syncthreads();

    uint32_t hloc, mloc;
    asm("{ .reg .u64 t; cvta.to.shared.u64 t, %1; cvt.u32.u64 %0, t; }"
        : "=r"(hloc) : "l"(&h_buf[0][0]));
    asm("{ .reg .u64 t; cvta.to.shared.u64 t, %1; cvt.u32.u64 %0, t; }"
        : "=r"(mloc) : "l"(&mbar[0]));
    uint32_t hpeer, mpeer;
    asm("mapa.shared::cluster.u32 %0, %1, %2;" : "=r"(hpeer) : "r"(hloc), "r"(rank ^ 1));
    asm("mapa.shared::cluster.u32 %0, %1, %2;" : "=r"(mpeer) : "r"(mloc), "r"(rank ^ 1));

    const size_t zbase = (size_t)batch * S_LEN * H_DIM;

    float zc = 0.f, zn = 0.f;
    if (tid < 128) zc = Z[zbase + rank * 128 + tid];   // t = 0 prefetch

    // mbarriers live in both CTAs before any st.async targets them
    asm volatile("barrier.cluster.arrive.aligned;" ::: "memory");
    asm volatile("barrier.cluster.wait.aligned;"   ::: "memory");

    for (int t = 0; t < S_LEN; t++) {
        const int cur = t & 1;
        const int nxt = cur ^ 1;

        // Arm phase t at loop top (off the reducer tail). Safe: phase t-2 of
        // mbar[t&1] was consumed by late warps before FMA(t-1); S1(t-1)
        // orders every thread -- including tid0 -- after that point.
        if (tid == 0)
            asm volatile("mbarrier.arrive.expect_tx.shared.b64 _, [%0], 512;"
                         :: "r"(mloc + (uint32_t)((t & 1) * 8)) : "memory");

        // Prefetch next z early (max slack before it is consumed next step).
        if (tid < 128 && t + 1 < S_LEN)
            zn = Z[zbase + (size_t)(t + 1) * H_DIM + rank * 128 + tid];

        // Late warps: wait for peer's phase-(t-1) st.async bytes.
        // Early warps: their h chunk arrived via STS + S2 of step t-1.
        if (t > 0 && is_late)
            mbar_wait(mloc + (uint32_t)(((t - 1) & 1) * 8),
                      (uint32_t)(((t - 1) >> 1) & 1));

        // FMA: 4 warp-uniform LDS.128 of h (broadcast), 4 rows per lane.
        const ulonglong2* h8 =
            reinterpret_cast<const ulonglong2*>(h_buf[cur] + c * 16);
        unsigned long long aA = 0ULL, aB = 0ULL, aC = 0ULL, aD = 0ULL;
#pragma unroll
        for (int j = 0; j < 4; j++) {
            ulonglong2 hv = h8[j];
            fma2(aA, wA[2 * j], hv.x); fma2(aA, wA[2 * j + 1], hv.y);
            fma2(aB, wB[2 * j], hv.x); fma2(aB, wB[2 * j + 1], hv.y);
            fma2(aC, wC[2 * j], hv.x); fma2(aC, wC[2 * j + 1], hv.y);
            fma2(aD, wD[2 * j], hv.x); fma2(aD, wD[2 * j + 1], hv.y);
        }
        {
            float2 u;
            u = unpack2(aA); stage[l][c]      = u.x + u.y;
            u = unpack2(aB); stage[l + 32][c] = u.x + u.y;
            u = unpack2(aC); stage[l + 64][c] = u.x + u.y;
            u = unpack2(aD); stage[l + 96][c] = u.x + u.y;
        }
        __syncthreads();                       // S1: all partials staged

        if (tid < 128) {
            // Pairwise tree over 16 partials (depth 4).
            float q0 = stage[tid][0],  q1 = stage[tid][1];
            float q2 = stage[tid][2],  q3 = stage[tid][3];
            float q4 = stage[tid][4],  q5 = stage[tid][5];
            float q6 = stage[tid][6],  q7 = stage[tid][7];
            float q8 = stage[tid][8],  q9 = stage[tid][9];
            float qa = stage[tid][10], qb = stage[tid][11];
            float qc = stage[tid][12], qd = stage[tid][13];
            float qe = stage[tid][14], qf = stage[tid][15];
            float sA = ((q0 + q1) + (q2 + q3)) + ((q4 + q5) + (q6 + q7));
            float sB = ((q8 + q9) + (qa + qb)) + ((qc + qd) + (qe + qf));
            float hv = fast_tanh((sA + sB) + zc);
            const int gr = rank * 128 + tid;
            const uint32_t off = (uint32_t)((nxt * H_DIM + gr) * 4);
            // Peer copy first (start DSMEM transit ASAP), completes peer's mbar.
            asm volatile(
                "st.async.shared::cluster.mbarrier::complete_tx::bytes.b32 [%0], %1, [%2];"
                :: "r"(hpeer + off), "f"(hv),
                   "r"(mpeer + (uint32_t)((t & 1) * 8)) : "memory");
            // Local copy: plain smem store, ordered by S2.
            h_buf[nxt][gr] = hv;
            Hout[zbase + (size_t)t * H_DIM + gr] = hv;   // fire-and-forget
        }
        __syncthreads();                       // S2: local h visible to early warps
        zc = zn;
    }

    // Drain: last step's st.async must land before SMEM is torn down.
    mbar_wait(mloc + (uint32_t)(((S_LEN - 1) & 1) * 8),
              (uint32_t)(((S_LEN - 1) >> 1) & 1));
    asm volatile("barrier.cluster.arrive.aligned;" ::: "memory");
    asm volatile("barrier.cluster.wait.aligned;"   ::: "memory");
}

// ---------------------------------------------------------------------------
extern "C" void kernel_launch(void* const* d_in, const int* in_sizes, int n_in,
                              void* d_out, int out_size)
{
    const float* x    = (const float*)d_in[0];
    const float* U0   = (const float*)d_in[1];
    const float* bU0  = (const float*)d_in[2];
    const float* W0   = (const float*)d_in[3];
    const float* bW0  = (const float*)d_in[4];
    const float* U1   = (const float*)d_in[5];
    const float* bU1  = (const float*)d_in[6];
    const float* W1   = (const float*)d_in[7];
    const float* bW1  = (const float*)d_in[8];
    const float* fc1W = (const float*)d_in[9];
    const float* fc1b = (const float*)d_in[10];
    const float* fc2W = (const float*)d_in[11];
    const float* fc2b = (const float*)d_in[12];
    const float* fc3W = (const float*)d_in[13];
    const float* fc3b = (const float*)d_in[14];
    float* out = (float*)d_out;

    float *bufA, *bufB, *bufC, *bufD, *M, *hW, *hb;
    cudaGetSymbolAddress((void**)&bufA, g_bufA);
    cudaGetSymbolAddress((void**)&bufB, g_bufB);
    cudaGetSymbolAddress((void**)&bufC, g_bufC);
    cudaGetSymbolAddress((void**)&bufD, g_bufD);
    cudaGetSymbolAddress((void**)&M,    g_M);
    cudaGetSymbolAddress((void**)&hW,   g_hW);
    cudaGetSymbolAddress((void**)&hb,   g_hb);

    dim3 blk(256);
    dim3 g256(2, NROWS / 128);   // N = 256
    dim3 g64(1, NROWS / 128);    // N = 64

    // Head fusion precompute: W' = fc3W @ fc2W @ fc1W ; b' = fc3W(fc2W b1 + b2) + b3
    matmul_nn<<<H_DIM, H_DIM>>>(fc2W, fc1W, M);
    matmul_nn<<<O_DIM, H_DIM>>>(fc3W, M, hW);
    head_bias<<<1, H_DIM>>>(fc2W, fc1b, fc2b, fc3W, fc3b, hb);

    // 1) Z0 = x @ U0^T + bU0 + bW0
    sgemm_bias<<<g256, blk>>>(x, U0, bU0, bW0, bufA, NROWS, H_DIM, I_DIM);
    // 2) scan layer 0 -> H0  (128 CTAs = 64 clusters, 1 batch each)
    scan_rnn<<<128, 512>>>(bufA, W0, bufB);
    // 3) Z1 = H0 @ U1^T + bU1 + bW1
    sgemm_bias<<<g256, blk>>>(bufB, U1, bU1, bW1, bufC, NROWS, H_DIM, H_DIM);
    // 4) scan layer 1 -> H1
    scan_rnn<<<128, 512>>>(bufC, W1, bufD);
    // 5) fused head: out = H1 @ W'^T + b'
    sgemm_bias<<<g64, blk>>>(bufD, hW, hb, nullptr, out, NROWS, O_DIM, H_DIM);
}